// round 11
// baseline (speedup 1.0000x reference)
#include <cuda_runtime.h>
#include <cstdint>
#include <cstddef>

#define NN 1024
#define BB 32

// ---------------- device scratch (no allocations allowed) ----------------
static __device__ float2   g_tw[NN];        // W1024^{lane*brev5(j)} table
static __device__ float2   g_pa[BB * NN];   // analytic signal
static __device__ float2   g_bb[BB * NN];   // pa * SHIFT_FACTOR
static __device__ double   g_Sp[BB];        // sum of unnormalized shg
static __device__ double   g_Spt[BB];       // sum shg * tref
static __device__ double   g_St[BB];        // sum tref
static __device__ double   g_Stt[BB];       // sum tref^2
static __device__ unsigned g_M[BB];         // max shg (float bits)
static __device__ int      g_first[BB];
static __device__ int      g_last[BB];
static __device__ unsigned g_ctr;           // k_shg completed-CTA counter

__device__ __forceinline__ int br5(int j) {
    return (int)(__brev((unsigned)j) >> 27);
}

// ---------------- fully unrolled radix-2 DIF FFT-32 in registers ----------
// input natural order, output bit-reversed: out[j] = X[brev5(j)]
__device__ __forceinline__ void fft32(float* ar, float* ai) {
    const float W32r[16] = {
        1.00000000f, 0.98078528f, 0.92387953f, 0.83146961f,
        0.70710678f, 0.55557023f, 0.38268343f, 0.19509032f,
        0.00000000f,-0.19509032f,-0.38268343f,-0.55557023f,
       -0.70710678f,-0.83146961f,-0.92387953f,-0.98078528f };
    const float W32i[16] = {
        0.00000000f,-0.19509032f,-0.38268343f,-0.55557023f,
       -0.70710678f,-0.83146961f,-0.92387953f,-0.98078528f,
       -1.00000000f,-0.98078528f,-0.92387953f,-0.83146961f,
       -0.70710678f,-0.55557023f,-0.38268343f,-0.19509032f };
    #pragma unroll
    for (int st = 0; st < 5; st++) {
        const int h = 16 >> st;
        const int tstep = 1 << st;
        #pragma unroll
        for (int s = 0; s < 32; s += 2 * h) {
            #pragma unroll
            for (int j = 0; j < h; j++) {
                const int i0 = s + j, i1 = i0 + h;
                float ur = ar[i0], ui = ai[i0];
                float vr = ar[i1], vi = ai[i1];
                ar[i0] = ur + vr; ai[i0] = ui + vi;
                float dr = ur - vr, di = ui - vi;
                const int w = j * tstep;
                if (w == 0)      { ar[i1] = dr;  ai[i1] = di;  }
                else if (w == 8) { ar[i1] = di;  ai[i1] = -dr; }   // *(0,-1)
                else {
                    float wr = W32r[w], wi = W32i[w];
                    ar[i1] = dr * wr - di * wi;
                    ai[i1] = di * wr + dr * wi;
                }
            }
        }
    }
}

// FFT-1024: lane t holds x[t + 32*q] in reg q. Output: reg j of lane l holds
// X[l + 32*brev5(j)]. One padded 33x32 smem buffer reused for re and im.
__device__ __forceinline__ void fft1024(float* xr, float* xi,
                                        float* sm, int lane) {
    fft32(xr, xi);                 // per-lane DFT over q
    #pragma unroll
    for (int j = 0; j < 32; j++) { // twiddle W1024^{lane * brev5(j)}
        float2 w = g_tw[j * 32 + lane];
        float r = xr[j] * w.x - xi[j] * w.y;
        xi[j]   = xi[j] * w.x + xr[j] * w.y;
        xr[j]   = r;
    }
    __syncwarp();
    #pragma unroll
    for (int j = 0; j < 32; j++) sm[br5(j) * 33 + lane] = xr[j];
    __syncwarp();
    #pragma unroll
    for (int r = 0; r < 32; r++) xr[r] = sm[lane * 33 + r];
    __syncwarp();
    #pragma unroll
    for (int j = 0; j < 32; j++) sm[br5(j) * 33 + lane] = xi[j];
    __syncwarp();
    #pragma unroll
    for (int r = 0; r < 32; r++) xi[r] = sm[lane * 33 + r];
    __syncwarp();
    fft32(xr, xi);                 // DFT over former lane index
}

// ---------------- K0: twiddles + bounds + accumulator/output reset --------
__global__ void __launch_bounds__(128) k_init(const float* __restrict__ label,
                                              float* __restrict__ out) {
    int tid = threadIdx.x, lane = tid & 31, warp = tid >> 5;
    // twiddles: 8 CTAs x 128 threads = 1024 entries
    int i = blockIdx.x * 128 + tid;
    int j = i >> 5, t = i & 31;
    int e = (t * br5(j)) & 1023;
    float s, cc;
    sincospif(-(float)e * (1.0f / 512.0f), &s, &cc);
    g_tw[i] = make_float2(cc, s);

    // per-batch pulse bounds: warp wg handles batch wg
    int b = blockIdx.x * 4 + warp;
    const float* lab = label + b * 2 * NN;
    int fr = NN, lr2 = -1, fi = NN, li2 = -1;
    #pragma unroll
    for (int q = 0; q < 32; q++) {
        int tt = lane + 32 * q;
        float lr = lab[tt], li = lab[NN + tt];
        if (fabsf(lr) > 0.01f) { fr = min(fr, tt); lr2 = max(lr2, tt); }
        if (fabsf(li) > 0.01f) { fi = min(fi, tt); li2 = max(li2, tt); }
    }
    #pragma unroll
    for (int o = 16; o; o >>= 1) {
        fr  = min(fr,  __shfl_xor_sync(0xffffffffu, fr, o));
        lr2 = max(lr2, __shfl_xor_sync(0xffffffffu, lr2, o));
        fi  = min(fi,  __shfl_xor_sync(0xffffffffu, fi, o));
        li2 = max(li2, __shfl_xor_sync(0xffffffffu, li2, o));
    }
    if (lane == 0) {
        if (fr == NN)  fr = 0;
        if (fi == NN)  fi = 0;
        if (lr2 < 0)   lr2 = NN - 1;
        if (li2 < 0)   li2 = NN - 1;
        g_first[b] = min(fr, fi);
        g_last[b]  = max(lr2, li2);
    }

    if (blockIdx.x == 0) {
        if (tid < BB) {
            g_Sp[tid] = 0.0; g_Spt[tid] = 0.0;
            g_St[tid] = 0.0; g_Stt[tid] = 0.0;
            g_M[tid] = 0u;
        }
        if (tid == 0) { out[0] = 0.f; g_ctr = 0u; }
    }
}

// ---------------- K1: Hilbert + SHIFT_FACTOR fold (pure) ------------------
__global__ void __launch_bounds__(128) k_hilbert(const float* __restrict__ pred) {
    __shared__ float sm[4][33 * 32];
    int warp = threadIdx.x >> 5, lane = threadIdx.x & 31;
    int b = blockIdx.x * 4 + warp;

    float xr[32], xi[32];
    const float* p = pred + b * NN;
    #pragma unroll
    for (int q = 0; q < 32; q++) { xr[q] = p[lane + 32 * q]; xi[q] = 0.f; }

    fft1024(xr, xi, sm[warp], lane);

    float yr[32], yi[32];
    #pragma unroll
    for (int p2 = 0; p2 < 32; p2++) {
        int j = br5(p2);                 // source reg with freq lane + 32*p2
        int k = lane + 32 * p2;
        float f = (k > 512) ? 2.f : ((k == 512) ? 1.f : 0.f);
        yr[p2] =  xr[j] * f;
        yi[p2] = -xi[j] * f;
    }
    fft1024(yr, yi, sm[warp], lane);  // ifft via conj trick

    const float phi = (float)(2.0 * 1.175e15 * 1.5e-15);
    #pragma unroll
    for (int j = 0; j < 32; j++) {
        int m = lane + 32 * br5(j);
        float prr =  yr[j] * (1.f / 1024.f);
        float pii = -yi[j] * (1.f / 1024.f);
        g_pa[b * NN + m] = make_float2(prr, pii);
        float argf = phi * (float)(m - 512);
        float si, cr;
        sincosf(argf, &si, &cr);                 // SF = cr - i*si
        g_bb[b * NN + m] = make_float2(prr * cr + pii * si,
                                       pii * cr - prr * si);
    }
}

// ---------------- K2: SHG rows + MSE slice + last-CTA frog ----------------
__global__ void __launch_bounds__(128) k_shg(const float* __restrict__ tref,
                                             const float* __restrict__ label,
                                             float* __restrict__ out) {
    __shared__ float sm[4][33 * 32];
    __shared__ float s_acc[4][4];
    __shared__ float s_mx[4];
    __shared__ float s_mse[4];
    __shared__ bool  s_last;
    int warp = threadIdx.x >> 5, lane = threadIdx.x & 31;
    int w = blockIdx.x * 4 + warp;
    int b = w >> 10;          // 1024 rows per batch; whole CTA shares b
    int d = w & 1023;

    const float2* pb = g_bb + b * NN;
    const float2* pa = g_pa + b * NN;
    float xr[32], xi[32];
    #pragma unroll
    for (int q = 0; q < 32; q++) {
        int n = lane + 32 * q;
        float2 bv = pb[n];
        float2 av = pa[(n - d + 512) & 1023];
        xr[q] = bv.x * av.x - bv.y * av.y;
        xi[q] = bv.x * av.y + bv.y * av.x;
    }

    fft1024(xr, xi, sm[warp], lane);

    const float* trow = tref + (size_t)(b * 1024 + d) * 1024;
    float sp = 0.f, spt = 0.f, st = 0.f, stt = 0.f, mx = 0.f;
    #pragma unroll
    for (int j = 0; j < 32; j++) {
        float m = xr[j] * xr[j] + xi[j] * xi[j];
        int col = (lane + 32 * br5(j) + 512) & 1023;  // output fftshift remap
        float tv = __ldcs(trow + col);
        sp += m; spt += m * tv; st += tv; stt += tv * tv;
        mx = fmaxf(mx, m);
    }
    #pragma unroll
    for (int o = 16; o; o >>= 1) {
        sp  += __shfl_xor_sync(0xffffffffu, sp, o);
        spt += __shfl_xor_sync(0xffffffffu, spt, o);
        st  += __shfl_xor_sync(0xffffffffu, st, o);
        stt += __shfl_xor_sync(0xffffffffu, stt, o);
        mx = fmaxf(mx, __shfl_xor_sync(0xffffffffu, mx, o));
    }
    if (lane == 0) {
        s_acc[warp][0] = sp; s_acc[warp][1] = spt;
        s_acc[warp][2] = st; s_acc[warp][3] = stt;
        s_mx[warp] = mx;
    }

    // ---- MSE slice: CTAs 0..31 handle batch blockIdx.x -------------------
    if (blockIdx.x < BB) {
        int b2 = blockIdx.x;
        const float* lab = label + b2 * 2 * NN;
        int first = g_first[b2], last = g_last[b2];
        float s = 0.f;
        #pragma unroll
        for (int q = 0; q < 8; q++) {
            int t = threadIdx.x + 128 * q;
            float2 pav = g_pa[b2 * NN + t];
            float prr = pav.x, pii = pav.y;
            float lr = lab[t], li = lab[NN + t];
            bool inr = (t >= first) && (t < last);
            float pm = inr ? 10.f : 1.f;
            float d1 = prr - lr, d2 = pii - li;
            float d3 = (prr * prr + pii * pii) - (lr * lr + li * li);
            float dph = atan2f(pii, prr) - atan2f(li, lr);
            s += (d1 * d1 + d2 * d2 + d3 * d3) * pm + (inr ? dph * dph : 0.f);
        }
        #pragma unroll
        for (int o = 16; o; o >>= 1) s += __shfl_xor_sync(0xffffffffu, s, o);
        if (lane == 0) s_mse[warp] = s;
    }

    __syncthreads();
    if (threadIdx.x == 0) {
        double a0 = 0, a1 = 0, a2 = 0, a3 = 0; float mm = 0.f;
        #pragma unroll
        for (int i2 = 0; i2 < 4; i2++) {
            a0 += (double)s_acc[i2][0]; a1 += (double)s_acc[i2][1];
            a2 += (double)s_acc[i2][2]; a3 += (double)s_acc[i2][3];
            mm = fmaxf(mm, s_mx[i2]);
        }
        atomicAdd(&g_Sp[b],  a0);
        atomicAdd(&g_Spt[b], a1);
        atomicAdd(&g_St[b],  a2);
        atomicAdd(&g_Stt[b], a3);
        atomicMax(&g_M[b], __float_as_uint(mm));
        if (blockIdx.x < BB) {
            float ss = s_mse[0] + s_mse[1] + s_mse[2] + s_mse[3];
            atomicAdd(out, ss * (1.f / (4.f * 1024.f * 32.f)));  // /WSUM /N /B
        }
        // acq_rel counter: orders prior atomics without any L1 flush
        unsigned old;
        asm volatile("atom.acq_rel.gpu.add.u32 %0, [%1], %2;"
                     : "=r"(old) : "l"(&g_ctr), "r"(1u) : "memory");
        s_last = (old == (unsigned)(gridDim.x - 1));
    }
    __syncthreads();
    // ---- last-CTA frog finalize (reads via L2, atomics never touched L1) --
    if (s_last && threadIdx.x < BB) {
        int bi = threadIdx.x;
        double M   = (double)__uint_as_float(__ldcg(&g_M[bi]));
        double sp2 = __ldcg(&g_Sp[bi]);
        double spt2= __ldcg(&g_Spt[bi]);
        double st2 = __ldcg(&g_St[bi]);
        double stt2= __ldcg(&g_Stt[bi]);
        double mu  = (spt2 / M) / stt2;
        double dif = sp2 / M - mu * st2;
        float v = (float)(fabs(dif) * (1.0 / 1024.0)) * (1.f / 32.f);
        #pragma unroll
        for (int o = 16; o; o >>= 1) v += __shfl_xor_sync(0xffffffffu, v, o);
        if (bi == 0) atomicAdd(out, v);
    }
}

// ---------------- launch ---------------------------------------------------
extern "C" void kernel_launch(void* const* d_in, const int* in_sizes, int n_in,
                              void* d_out, int out_size) {
    (void)in_sizes; (void)n_in; (void)out_size;
    const float* pred  = (const float*)d_in[0];   // (32, 1024)
    const float* label = (const float*)d_in[1];   // (32, 2048)
    const float* shg   = (const float*)d_in[2];   // (32, 1, 1024, 1024)
    float* out = (float*)d_out;

    k_init<<<8, 128>>>(label, out);
    k_hilbert<<<8, 128>>>(pred);
    k_shg<<<8192, 128>>>(shg, label, out);
}

// round 13
// speedup vs baseline: 1.1215x; 1.1215x over previous
#include <cuda_runtime.h>
#include <cstdint>
#include <cstddef>

#define NN 1024
#define BB 32

// ---------------- device scratch (no allocations allowed) ----------------
static __device__ float2   g_tw[NN];        // W1024^{lane*brev5(j)} table
static __device__ float2   g_pa[BB * NN];   // analytic signal
static __device__ float2   g_bb[BB * NN];   // pa * SHIFT_FACTOR
static __device__ double   g_Sp[BB];        // sum of unnormalized shg
static __device__ double   g_Spt[BB];       // sum shg * tref
static __device__ double   g_St[BB];        // sum tref
static __device__ double   g_Stt[BB];       // sum tref^2
static __device__ unsigned g_M[BB];         // max shg (float bits)

__device__ __forceinline__ int br5(int j) {
    return (int)(__brev((unsigned)j) >> 27);
}

// ---------------- fully unrolled radix-2 DIF FFT-32 in registers ----------
// input natural order, output bit-reversed: out[j] = X[brev5(j)]
__device__ __forceinline__ void fft32(float* ar, float* ai) {
    const float W32r[16] = {
        1.00000000f, 0.98078528f, 0.92387953f, 0.83146961f,
        0.70710678f, 0.55557023f, 0.38268343f, 0.19509032f,
        0.00000000f,-0.19509032f,-0.38268343f,-0.55557023f,
       -0.70710678f,-0.83146961f,-0.92387953f,-0.98078528f };
    const float W32i[16] = {
        0.00000000f,-0.19509032f,-0.38268343f,-0.55557023f,
       -0.70710678f,-0.83146961f,-0.92387953f,-0.98078528f,
       -1.00000000f,-0.98078528f,-0.92387953f,-0.83146961f,
       -0.70710678f,-0.55557023f,-0.38268343f,-0.19509032f };
    #pragma unroll
    for (int st = 0; st < 5; st++) {
        const int h = 16 >> st;
        const int tstep = 1 << st;
        #pragma unroll
        for (int s = 0; s < 32; s += 2 * h) {
            #pragma unroll
            for (int j = 0; j < h; j++) {
                const int i0 = s + j, i1 = i0 + h;
                float ur = ar[i0], ui = ai[i0];
                float vr = ar[i1], vi = ai[i1];
                ar[i0] = ur + vr; ai[i0] = ui + vi;
                float dr = ur - vr, di = ui - vi;
                const int w = j * tstep;
                if (w == 0)      { ar[i1] = dr;  ai[i1] = di;  }
                else if (w == 8) { ar[i1] = di;  ai[i1] = -dr; }   // *(0,-1)
                else {
                    float wr = W32r[w], wi = W32i[w];
                    ar[i1] = dr * wr - di * wi;
                    ai[i1] = di * wr + dr * wi;
                }
            }
        }
    }
}

// FFT-1024: lane t holds x[t + 32*q] in reg q. Output: reg j of lane l holds
// X[l + 32*brev5(j)]. One padded 33x32 smem buffer reused for re and im.
__device__ __forceinline__ void fft1024(float* xr, float* xi,
                                        float* sm, int lane) {
    fft32(xr, xi);                 // per-lane DFT over q
    #pragma unroll
    for (int j = 0; j < 32; j++) { // twiddle W1024^{lane * brev5(j)}
        float2 w = g_tw[j * 32 + lane];
        float r = xr[j] * w.x - xi[j] * w.y;
        xi[j]   = xi[j] * w.x + xr[j] * w.y;
        xr[j]   = r;
    }
    __syncwarp();
    #pragma unroll
    for (int j = 0; j < 32; j++) sm[br5(j) * 33 + lane] = xr[j];
    __syncwarp();
    #pragma unroll
    for (int r = 0; r < 32; r++) xr[r] = sm[lane * 33 + r];
    __syncwarp();
    #pragma unroll
    for (int j = 0; j < 32; j++) sm[br5(j) * 33 + lane] = xi[j];
    __syncwarp();
    #pragma unroll
    for (int r = 0; r < 32; r++) xi[r] = sm[lane * 33 + r];
    __syncwarp();
    fft32(xr, xi);                 // DFT over former lane index
}

// ---------------- K0: twiddle table + accumulator/output reset ------------
__global__ void __launch_bounds__(256) k_init(float* __restrict__ out) {
    int tid = threadIdx.x;
    #pragma unroll
    for (int c = 0; c < 4; c++) {
        int i = tid + 256 * c;
        int j = i >> 5, t = i & 31;
        int e = (t * br5(j)) & 1023;
        float s, cc;
        sincospif(-(float)e * (1.0f / 512.0f), &s, &cc);
        g_tw[i] = make_float2(cc, s);
    }
    if (tid < BB) {
        g_Sp[tid] = 0.0; g_Spt[tid] = 0.0;
        g_St[tid] = 0.0; g_Stt[tid] = 0.0;
        g_M[tid] = 0u;
    }
    if (tid == 0) out[0] = 0.f;
}

// ---------------- K1: Hilbert (analytic signal) + SHIFT_FACTOR fold -------
__global__ void __launch_bounds__(128) k_hilbert(const float* __restrict__ pred) {
    __shared__ float sm[4][33 * 32];
    int warp = threadIdx.x >> 5, lane = threadIdx.x & 31;
    int b = blockIdx.x * 4 + warp;

    float xr[32], xi[32];
    const float* p = pred + b * NN;
    #pragma unroll
    for (int q = 0; q < 32; q++) { xr[q] = p[lane + 32 * q]; xi[q] = 0.f; }

    fft1024(xr, xi, sm[warp], lane);

    float yr[32], yi[32];
    #pragma unroll
    for (int p2 = 0; p2 < 32; p2++) {
        int j = br5(p2);
        int k = lane + 32 * p2;
        float f = (k > 512) ? 2.f : ((k == 512) ? 1.f : 0.f);
        yr[p2] =  xr[j] * f;
        yi[p2] = -xi[j] * f;
    }
    fft1024(yr, yi, sm[warp], lane);   // ifft via conj trick

    const float phi = (float)(2.0 * 1.175e15 * 1.5e-15);
    #pragma unroll
    for (int j = 0; j < 32; j++) {
        int m = lane + 32 * br5(j);
        float prr =  yr[j] * (1.f / 1024.f);
        float pii = -yi[j] * (1.f / 1024.f);
        g_pa[b * NN + m] = make_float2(prr, pii);
        float argf = phi * (float)(m - 512);
        float si, cr;
        sincosf(argf, &si, &cr);                 // SF = cr - i*si
        g_bb[b * NN + m] = make_float2(prr * cr + pii * si,
                                       pii * cr - prr * si);
    }
}

// ---------------- K2: SHG rows — FFT + streaming reduction (R2 body) ------
__global__ void __launch_bounds__(128) k_shg(const float* __restrict__ tref) {
    __shared__ float sm[4][33 * 32];
    __shared__ float s_acc[4][4];
    __shared__ float s_mx[4];
    int warp = threadIdx.x >> 5, lane = threadIdx.x & 31;
    int w = blockIdx.x * 4 + warp;
    int b = w >> 10;          // 1024 rows per batch; whole CTA shares b
    int d = w & 1023;

    const float2* pb = g_bb + b * NN;
    const float2* pa = g_pa + b * NN;
    float xr[32], xi[32];
    #pragma unroll
    for (int q = 0; q < 32; q++) {
        int n = lane + 32 * q;
        float2 bv = pb[n];
        float2 av = pa[(n - d + 512) & 1023];
        xr[q] = bv.x * av.x - bv.y * av.y;
        xi[q] = bv.x * av.y + bv.y * av.x;
    }

    fft1024(xr, xi, sm[warp], lane);

    const float* trow = tref + (size_t)(b * 1024 + d) * 1024;
    float sp = 0.f, spt = 0.f, st = 0.f, stt = 0.f, mx = 0.f;
    #pragma unroll
    for (int j = 0; j < 32; j++) {
        float m = xr[j] * xr[j] + xi[j] * xi[j];
        int col = (lane + 32 * br5(j) + 512) & 1023;  // output fftshift remap
        float tv = __ldcs(trow + col);
        sp += m; spt += m * tv; st += tv; stt += tv * tv;
        mx = fmaxf(mx, m);
    }
    #pragma unroll
    for (int o = 16; o; o >>= 1) {
        sp  += __shfl_xor_sync(0xffffffffu, sp, o);
        spt += __shfl_xor_sync(0xffffffffu, spt, o);
        st  += __shfl_xor_sync(0xffffffffu, st, o);
        stt += __shfl_xor_sync(0xffffffffu, stt, o);
        mx = fmaxf(mx, __shfl_xor_sync(0xffffffffu, mx, o));
    }
    if (lane == 0) {
        s_acc[warp][0] = sp; s_acc[warp][1] = spt;
        s_acc[warp][2] = st; s_acc[warp][3] = stt;
        s_mx[warp] = mx;
    }
    __syncthreads();
    if (threadIdx.x == 0) {
        double a0 = 0, a1 = 0, a2 = 0, a3 = 0; float mm = 0.f;
        #pragma unroll
        for (int i2 = 0; i2 < 4; i2++) {
            a0 += (double)s_acc[i2][0]; a1 += (double)s_acc[i2][1];
            a2 += (double)s_acc[i2][2]; a3 += (double)s_acc[i2][3];
            mm = fmaxf(mm, s_mx[i2]);
        }
        atomicAdd(&g_Sp[b],  a0);
        atomicAdd(&g_Spt[b], a1);
        atomicAdd(&g_St[b],  a2);
        atomicAdd(&g_Stt[b], a3);
        atomicMax(&g_M[b], __float_as_uint(mm));
    }
}

// ---------------- K3: per-batch MSE + FROG (1024 threads, 1 elem/thread) --
__global__ void __launch_bounds__(1024) k_loss(const float* __restrict__ label,
                                               float* __restrict__ out) {
    __shared__ int   s_fr[32], s_lr[32], s_fi[32], s_li[32];
    __shared__ float s_s[32];
    __shared__ int   s_first, s_last;
    int b = blockIdx.x;
    int tid = threadIdx.x, lane = tid & 31, warp = tid >> 5;
    const float* lab = label + b * 2 * NN;

    // pass 1: bounds, 1 element per thread
    float lr = lab[tid], li = lab[NN + tid];
    bool hr = fabsf(lr) > 0.01f, hi = fabsf(li) > 0.01f;
    int fr  = hr ? tid : NN;
    int lr2 = hr ? tid : -1;
    int fi  = hi ? tid : NN;
    int li2 = hi ? tid : -1;
    #pragma unroll
    for (int o = 16; o; o >>= 1) {
        fr  = min(fr,  __shfl_xor_sync(0xffffffffu, fr, o));
        lr2 = max(lr2, __shfl_xor_sync(0xffffffffu, lr2, o));
        fi  = min(fi,  __shfl_xor_sync(0xffffffffu, fi, o));
        li2 = max(li2, __shfl_xor_sync(0xffffffffu, li2, o));
    }
    if (lane == 0) { s_fr[warp] = fr; s_lr[warp] = lr2; s_fi[warp] = fi; s_li[warp] = li2; }
    __syncthreads();
    if (warp == 0) {
        int a = s_fr[lane], c = s_lr[lane], e = s_fi[lane], g = s_li[lane];
        #pragma unroll
        for (int o = 16; o; o >>= 1) {
            a = min(a, __shfl_xor_sync(0xffffffffu, a, o));
            c = max(c, __shfl_xor_sync(0xffffffffu, c, o));
            e = min(e, __shfl_xor_sync(0xffffffffu, e, o));
            g = max(g, __shfl_xor_sync(0xffffffffu, g, o));
        }
        if (lane == 0) {
            if (a == NN) a = 0;
            if (e == NN) e = 0;
            if (c < 0)   c = NN - 1;
            if (g < 0)   g = NN - 1;
            s_first = min(a, e);
            s_last  = max(c, g);
        }
    }
    __syncthreads();
    int first = s_first, last = s_last;

    // pass 2: masked MSE terms, 1 element per thread
    float2 pav = g_pa[b * NN + tid];
    float pr = pav.x, pi = pav.y;
    bool inr = (tid >= first) && (tid < last);
    float pm = inr ? 10.f : 1.f;
    float d1 = pr - lr, d2 = pi - li;
    float d3 = (pr * pr + pi * pi) - (lr * lr + li * li);
    float dph = atan2f(pi, pr) - atan2f(li, lr);
    float s = (d1 * d1 + d2 * d2 + d3 * d3) * pm + (inr ? dph * dph : 0.f);

    #pragma unroll
    for (int o = 16; o; o >>= 1) s += __shfl_xor_sync(0xffffffffu, s, o);
    if (lane == 0) s_s[warp] = s;
    __syncthreads();
    if (tid == 0) {
        float ss = 0.f;
        #pragma unroll
        for (int i = 0; i < 32; i++) ss += s_s[i];
        float mse = ss * (1.f / (4.f * 1024.f));   // /N and /MSE_WSUM
        double M   = (double)__uint_as_float(g_M[b]);
        double mu  = (g_Spt[b] / M) / g_Stt[b];
        double dif = g_Sp[b] / M - mu * g_St[b];
        float frog = (float)(fabs(dif) * (1.0 / 1024.0));  // sqrt(r/N^2)
        atomicAdd(out, (mse + frog) * (1.f / 32.f));
    }
}

// ---------------- launch ---------------------------------------------------
extern "C" void kernel_launch(void* const* d_in, const int* in_sizes, int n_in,
                              void* d_out, int out_size) {
    (void)in_sizes; (void)n_in; (void)out_size;
    const float* pred  = (const float*)d_in[0];   // (32, 1024)
    const float* label = (const float*)d_in[1];   // (32, 2048)
    const float* shg   = (const float*)d_in[2];   // (32, 1, 1024, 1024)
    float* out = (float*)d_out;

    k_init<<<1, 256>>>(out);
    k_hilbert<<<8, 128>>>(pred);
    k_shg<<<8192, 128>>>(shg);
    k_loss<<<32, 1024>>>(label, out);
}